// round 6
// baseline (speedup 1.0000x reference)
#include <cuda_runtime.h>
#include <math.h>

// RoI max pooling (Caffe-style), bit-matching the JAX/XLA reference.
//   x    : [B=2, C=128, H=64, W=64] fp32
//   rois : [N=256, 5]  (batch_idx, x1, y1, x2, y2) image coords
//   out  : [N, C, 7, 7] fp32
//
// Plan (R6): channels-last. R4/R5 profiles showed the thread-per-output
// kernel is NOT issue-bound; it is bound by divergent per-lane pooling
// windows fragmenting L1 wavefronts. Fix: transpose x -> xt[B,H,W,C] once,
// then give each warp 32 consecutive channels of the SAME bin: uniform
// loop bounds (zero divergence) and every gather is one contiguous 128B
// line. Outputs staged in padded smem and written coalesced.
//
// CRITICAL (bit-exactness): XLA rewrites `roi / 7` into `roi * fl32(1/7)`.
// Must use the same reciprocal multiply or floor/ceil bin boundaries shift
// by 1 ulp on 7-divisible roi extents (caused rel_err 9.6e-2 in R1/R3).

#define B_  2
#define C_  128
#define H_  64
#define W_  64
#define S_  (H_ * W_)       // 4096
#define N_  256
#define OUTH_ 7
#define OUTW_ 7
#define NB_  (OUTH_ * OUTW_)  // 49
#define SCALE_ (1.0f / 16.0f)
#define RCP7_  (1.0f / 7.0f)   // fp32 RN: 0x3E124925

// channels-last scratch copy of x (static device global -> no allocation)
__device__ float g_xt[B_ * S_ * C_];   // [b][h][w][c], 16 MB

// ---------------------------------------------------------------- transpose
// x[b][c][s] -> xt[b][s][c], 32x32 smem tiles, fully coalesced both sides.
__global__ void transpose_kernel(const float* __restrict__ x) {
    __shared__ float t[32][33];
    const int b  = blockIdx.z;
    const int s0 = blockIdx.x * 32;
    const int c0 = blockIdx.y * 32;
    #pragma unroll
    for (int i = 0; i < 4; ++i) {
        const int c = c0 + threadIdx.y + i * 8;
        t[threadIdx.y + i * 8][threadIdx.x] =
            x[((size_t)b * C_ + c) * S_ + s0 + threadIdx.x];
    }
    __syncthreads();
    #pragma unroll
    for (int i = 0; i < 4; ++i) {
        const int s = s0 + threadIdx.y + i * 8;
        g_xt[((size_t)b * S_ + s) * C_ + c0 + threadIdx.x] =
            t[threadIdx.x][threadIdx.y + i * 8];
    }
}

// --------------------------------------------------------------------- pool
// One block per roi (grid = 256, block = 256 threads).
// Thread t: channel c = t & 127, bins (t>>7), (t>>7)+2, ... (<49).
// Lanes of a warp share the bin -> uniform loops, contiguous 128B gathers.
__global__ void roi_pool_kernel(const float* __restrict__ rois,
                                float* __restrict__ out) {
    __shared__ int4  sb[NB_];            // clamped {hs, he, ws, we} per bin
    __shared__ int   sbidx;
    __shared__ float tile[NB_ * 129];    // padded: bank-conflict-free readout

    const int n = blockIdx.x;
    const int t = threadIdx.x;

    if (t < NB_) {
        const int ph = t / OUTW_;
        const int pw = t - ph * OUTW_;
        const float* r = rois + n * 5;
        const int xs = (int)rintf(r[1] * SCALE_);
        const int ys = (int)rintf(r[2] * SCALE_);
        const int xe = (int)rintf(r[3] * SCALE_);
        const int ye = (int)rintf(r[4] * SCALE_);
        const float roi_w = (float)max(xe - xs + 1, 1);
        const float roi_h = (float)max(ye - ys + 1, 1);
        // match XLA's divide -> multiply-by-reciprocal rewrite exactly
        const float bin_h = __fmul_rn(roi_h, RCP7_);
        const float bin_w = __fmul_rn(roi_w, RCP7_);
        int hs = (int)floorf(__fmul_rn((float)ph, bin_h)) + ys;
        int he = (int)ceilf(__fmul_rn((float)ph + 1.0f, bin_h)) + ys;
        int ws = (int)floorf(__fmul_rn((float)pw, bin_w)) + xs;
        int we = (int)ceilf(__fmul_rn((float)pw + 1.0f, bin_w)) + xs;
        hs = min(max(hs, 0), H_);
        he = min(max(he, 0), H_);
        ws = min(max(ws, 0), W_);
        we = min(max(we, 0), W_);
        sb[t] = make_int4(hs, he, ws, we);
        if (t == 0) sbidx = (int)r[0];
    }
    __syncthreads();

    const int c = t & (C_ - 1);
    const float* base = g_xt + (size_t)sbidx * (S_ * C_) + c;

    for (int bin = (t >> 7); bin < NB_; bin += 2) {
        const int4 b = sb[bin];   // uniform across the warp
        float m = -INFINITY;
        for (int h = b.x; h < b.y; ++h) {
            const float* rowp = base + (h * W_) * C_;
            for (int w = b.z; w < b.w; ++w) {
                m = fmaxf(m, __ldg(rowp + w * C_));
            }
        }
        const bool empty = (b.y <= b.x) || (b.w <= b.z);
        tile[bin * 129 + c] = empty ? 0.0f : m;
    }
    __syncthreads();

    // coalesced writeback: out[n][c][bin]
    float* outn = out + (size_t)n * (C_ * NB_);
    for (int o = t; o < C_ * NB_; o += 256) {
        const int co = o / NB_;
        const int bo = o - co * NB_;
        outn[o] = tile[bo * 129 + co];
    }
}

extern "C" void kernel_launch(void* const* d_in, const int* in_sizes, int n_in,
                              void* d_out, int out_size) {
    const float* x    = (const float*)d_in[0];
    const float* rois = (const float*)d_in[1];
    float* out = (float*)d_out;

    transpose_kernel<<<dim3(S_ / 32, C_ / 32, B_), dim3(32, 8)>>>(x);
    roi_pool_kernel<<<N_, 256>>>(rois, out);
}

// round 7
// speedup vs baseline: 3.3758x; 3.3758x over previous
#include <cuda_runtime.h>
#include <math.h>

// RoI max pooling (Caffe-style), bit-matching the JAX/XLA reference.
//   x    : [B=2, C=128, H=64, W=64] fp32
//   rois : [N=256, 5]  (batch_idx, x1, y1, x2, y2) image coords
//   out  : [N, C, 7, 7] fp32
//
// R7 plan: channels-last gathers (R6's wavefront win: warp = 32 consecutive
// channels of ONE bin -> uniform bounds, each load = one 128B line) but with
// restored parallelism: grid = (7, 256) = 1792 blocks x 256 threads
// (~12 blocks/SM), fixing R6's latency exposure (256 blocks, occ 17.6%).
//
// CRITICAL (bit-exactness): XLA rewrites `roi / 7` into `roi * fl32(1/7)`.
// Must use the same reciprocal multiply or floor/ceil bin boundaries shift
// by 1 ulp on 7-divisible roi extents (caused rel_err 9.6e-2 in R1/R3).

#define B_  2
#define C_  128
#define H_  64
#define W_  64
#define S_  (H_ * W_)        // 4096
#define N_  256
#define OUTH_ 7
#define OUTW_ 7
#define NB_  (OUTH_ * OUTW_) // 49
#define SCALE_ (1.0f / 16.0f)
#define RCP7_  (1.0f / 7.0f) // fp32 RN: 0x3E124925

// channels-last scratch copy of x (static device global -> no allocation), 4 MB
__device__ float g_xt[B_ * S_ * C_];   // [b][h][w][c]

// ---------------------------------------------------------------- transpose
// x[b][c][s] -> xt[b][s][c], 32x32 smem tiles, coalesced both sides.
__global__ void transpose_kernel(const float* __restrict__ x) {
    __shared__ float t[32][33];
    const int b  = blockIdx.z;
    const int s0 = blockIdx.x * 32;
    const int c0 = blockIdx.y * 32;
    #pragma unroll
    for (int i = 0; i < 4; ++i) {
        const int c = c0 + threadIdx.y + i * 8;
        t[threadIdx.y + i * 8][threadIdx.x] =
            x[((size_t)b * C_ + c) * S_ + s0 + threadIdx.x];
    }
    __syncthreads();
    #pragma unroll
    for (int i = 0; i < 4; ++i) {
        const int s = s0 + threadIdx.y + i * 8;
        g_xt[((size_t)b * S_ + s) * C_ + c0 + threadIdx.x] =
            t[threadIdx.x][threadIdx.y + i * 8];
    }
}

// --------------------------------------------------------------------- pool
// Block = (ph, n). 256 threads = 8 warps.
// Warp w: channels (w&3)*32 + lane; bins pw = (w>>2), (w>>2)+2, ... (<7).
// Lanes of a warp share the bin -> uniform loops, each gather = one 128B line.
__global__ void roi_pool_kernel(const float* __restrict__ rois,
                                float* __restrict__ out) {
    __shared__ int4  sb[OUTW_];           // clamped {hs, he, ws, we} per pw
    __shared__ int   sbidx;
    __shared__ float tile[OUTW_ * 129];   // [pw][c], padded rows

    const int ph = blockIdx.x;
    const int n  = blockIdx.y;
    const int t  = threadIdx.x;

    if (t < OUTW_) {
        const int pw = t;
        const float* r = rois + n * 5;
        const int xs = (int)rintf(r[1] * SCALE_);
        const int ys = (int)rintf(r[2] * SCALE_);
        const int xe = (int)rintf(r[3] * SCALE_);
        const int ye = (int)rintf(r[4] * SCALE_);
        const float roi_w = (float)max(xe - xs + 1, 1);
        const float roi_h = (float)max(ye - ys + 1, 1);
        // match XLA's divide -> multiply-by-reciprocal rewrite exactly
        const float bin_h = __fmul_rn(roi_h, RCP7_);
        const float bin_w = __fmul_rn(roi_w, RCP7_);
        int hs = (int)floorf(__fmul_rn((float)ph, bin_h)) + ys;
        int he = (int)ceilf(__fmul_rn((float)ph + 1.0f, bin_h)) + ys;
        int ws = (int)floorf(__fmul_rn((float)pw, bin_w)) + xs;
        int we = (int)ceilf(__fmul_rn((float)pw + 1.0f, bin_w)) + xs;
        hs = min(max(hs, 0), H_);
        he = min(max(he, 0), H_);
        ws = min(max(ws, 0), W_);
        we = min(max(we, 0), W_);
        sb[pw] = make_int4(hs, he, ws, we);
        if (t == 0) sbidx = (int)r[0];
    }
    __syncthreads();

    const int warpid = t >> 5;
    const int c      = ((warpid & 3) << 5) + (t & 31);
    const float* base = g_xt + (size_t)sbidx * (S_ * C_) + c;

    for (int pw = (warpid >> 2); pw < OUTW_; pw += 2) {
        const int4 b = sb[pw];   // uniform across the warp
        float m = -INFINITY;
        for (int h = b.x; h < b.y; ++h) {
            const float* rowp = base + (size_t)(h * W_) * C_;
            #pragma unroll 2
            for (int w = b.z; w < b.w; ++w) {
                m = fmaxf(m, __ldg(rowp + (size_t)w * C_));
            }
        }
        const bool empty = (b.y <= b.x) || (b.w <= b.z);
        tile[pw * 129 + c] = empty ? 0.0f : m;
    }
    __syncthreads();

    // near-coalesced writeback: out[n][c][ph*7 + pw]
    float* outn = out + (size_t)n * (C_ * NB_) + ph * OUTW_;
    for (int o = t; o < C_ * OUTW_; o += 256) {
        const int co = o / OUTW_;
        const int pwo = o - co * OUTW_;
        outn[(size_t)co * NB_ + pwo] = tile[pwo * 129 + co];
    }
}

extern "C" void kernel_launch(void* const* d_in, const int* in_sizes, int n_in,
                              void* d_out, int out_size) {
    const float* x    = (const float*)d_in[0];
    const float* rois = (const float*)d_in[1];
    float* out = (float*)d_out;

    transpose_kernel<<<dim3(S_ / 32, C_ / 32, B_), dim3(32, 8)>>>(x);
    roi_pool_kernel<<<dim3(OUTH_, N_), 256>>>(rois, out);
}